// round 16
// baseline (speedup 1.0000x reference)
#include <cuda_runtime.h>
#include <cuda_fp16.h>
#include <cstdint>

#define CDIM 128
#define NS1 74
#define PQ 72   // fp16 tile pitch (144B): conflict-free LDSM

__device__ float g_part[2][80][64][CDIM];   // 5.2 MB
__device__ float g_UV[2][64][CDIM];
__device__ unsigned short g_Ph[64][128];    // fp16 P
__device__ unsigned short g_Rh[64][128];    // fp16 R

// ---------------------------------------------------------------------------
// helpers
// ---------------------------------------------------------------------------
__device__ __forceinline__ unsigned sadr(const void* p) {
    return (unsigned)__cvta_generic_to_shared(p);
}
__device__ __forceinline__ uint32_t pkh2(float x0, float x1) {
    uint32_t d;
    asm("cvt.rn.f16x2.f32 %0, %2, %1;" : "=r"(d) : "f"(x0), "f"(x1));
    return d;
}
__device__ __forceinline__ void cvsth(unsigned short* hp, float4 a) {
    ((uint32_t*)hp)[0] = pkh2(a.x, a.y);
    ((uint32_t*)hp)[1] = pkh2(a.z, a.w);
}
__device__ __forceinline__ void ldmA(uint32_t* a, unsigned addr) {
    asm volatile("ldmatrix.sync.aligned.m8n8.x4.shared.b16 {%0,%1,%2,%3},[%4];"
        : "=r"(a[0]), "=r"(a[1]), "=r"(a[2]), "=r"(a[3]) : "r"(addr));
}
__device__ __forceinline__ void ldmAT(uint32_t* a, unsigned addr) {
    asm volatile("ldmatrix.sync.aligned.m8n8.x4.trans.shared.b16 {%0,%1,%2,%3},[%4];"
        : "=r"(a[0]), "=r"(a[1]), "=r"(a[2]), "=r"(a[3]) : "r"(addr));
}
__device__ __forceinline__ void ldmBT(uint32_t* b, unsigned addr) {
    asm volatile("ldmatrix.sync.aligned.m8n8.x2.trans.shared.b16 {%0,%1},[%2];"
        : "=r"(b[0]), "=r"(b[1]) : "r"(addr));
}
__device__ __forceinline__ void mma_h(float* d, const uint32_t* a, const uint32_t* b) {
    asm volatile("mma.sync.aligned.m16n8k16.row.col.f32.f16.f16.f32 "
        "{%0,%1,%2,%3},{%4,%5,%6,%7},{%8,%9},{%0,%1,%2,%3};"
        : "+f"(d[0]), "+f"(d[1]), "+f"(d[2]), "+f"(d[3])
        : "r"(a[0]), "r"(a[1]), "r"(a[2]), "r"(a[3]), "r"(b[0]), "r"(b[1]));
}
#define NEG4H(dst, src) { dst[0]=src[0]^0x80008000u; dst[1]=src[1]^0x80008000u; \
                          dst[2]=src[2]^0x80008000u; dst[3]=src[3]^0x80008000u; }
__device__ __forceinline__ void cpa16(void* s, const void* g) {
    unsigned sa = (unsigned)__cvta_generic_to_shared(s);
    asm volatile("cp.async.cg.shared.global [%0], [%1], 16;" :: "r"(sa), "l"(g));
}
__device__ __forceinline__ void cpa_commit() {
    asm volatile("cp.async.commit_group;" ::: "memory");
}
template<int NN> __device__ __forceinline__ void cpa_wait() {
    asm volatile("cp.async.wait_group %0;" :: "n"(NN) : "memory");
}

// ---------------------------------------------------------------------------
// Kernel 1 (R15 proven): U/V partials, fp16 single-pass, chunk loop.
// grid (74, 2 c-halves), block 256: 8 warps = 4 k-slabs(16) x 2 c-sub(32).
// ---------------------------------------------------------------------------
__global__ __launch_bounds__(256, 1) void k1_partial(
    const float* __restrict__ Qr, const float* __restrict__ Qi,
    const float* __restrict__ re, const float* __restrict__ im, int N)
{
    __shared__ unsigned short sQr[32][PQ], sQi[32][PQ];
    __shared__ unsigned short sRe[32][PQ], sIm[32][PQ];

    const int s  = blockIdx.x;
    const int c0 = blockIdx.y * 64;
    const int tid = threadIdx.x;
    const int nchunks = (N + 31) >> 5;
    const float4 f4z = make_float4(0.f, 0.f, 0.f, 0.f);

    const int lane = tid & 31, warp = tid >> 5;
    const int m0 = (warp & 3) * 16;
    const int cs = (warp >> 2) * 32;
    const int r8 = lane & 7, sel = lane >> 3;
    const int atrow = ((sel >> 1) & 1) * 8 + r8;
    const int atcol = m0 + (sel & 1) * 8;
    const int brow = lane & 15;
    const int gid = lane >> 2, tig = lane & 3;

    float u[4][4] = {};
    float v[4][4] = {};

    float4 qa[2], qb[2], xa[2], xb[2];
    auto ldchunk = [&](int ci) {
        #pragma unroll
        for (int q = 0; q < 2; q++) {
            int f = tid + 256 * q;
            int row = f >> 4, k4 = (f & 15) * 4;
            int n = ci * 32 + row;
            bool ok = (n < N);
            qa[q] = ok ? *(const float4*)(Qr + (long)n * 64 + k4) : f4z;
            qb[q] = ok ? *(const float4*)(Qi + (long)n * 64 + k4) : f4z;
            xa[q] = ok ? *(const float4*)(re + (long)n * 128 + c0 + k4) : f4z;
            xb[q] = ok ? *(const float4*)(im + (long)n * 128 + c0 + k4) : f4z;
        }
    };

    ldchunk(s);
    for (int t = 0;; t++) {
        int ci = s + t * NS1;
        if (ci >= nchunks) break;
        #pragma unroll
        for (int q = 0; q < 2; q++) {
            int f = tid + 256 * q;
            int row = f >> 4, k4 = (f & 15) * 4;
            cvsth(&sQr[row][k4], qa[q]);
            cvsth(&sQi[row][k4], qb[q]);
            cvsth(&sRe[row][k4], xa[q]);
            cvsth(&sIm[row][k4], xb[q]);
        }
        __syncthreads();
        int cin = ci + NS1;
        if (cin < nchunks) ldchunk(cin);

        #pragma unroll
        for (int ks = 0; ks < 2; ks++) {
            const int n0k = ks * 16;
            uint32_t qr[4], qi[4], nq[4];
            ldmAT(qr, sadr(&sQr[n0k + atrow][atcol]));
            ldmAT(qi, sadr(&sQi[n0k + atrow][atcol]));
            NEG4H(nq, qr);
            #pragma unroll
            for (int nt = 0; nt < 4; nt++) {
                uint32_t x[2], y[2];
                ldmBT(x, sadr(&sRe[n0k + brow][cs + nt * 8]));
                ldmBT(y, sadr(&sIm[n0k + brow][cs + nt * 8]));
                mma_h(u[nt], qr, x);
                mma_h(u[nt], qi, y);
                mma_h(v[nt], qi, x);
                mma_h(v[nt], nq, y);
            }
        }
        __syncthreads();
    }

    #pragma unroll
    for (int nt = 0; nt < 4; nt++) {
        int k = m0 + gid;
        int c = c0 + cs + nt * 8 + tig * 2;
        *(float2*)&g_part[0][s][k][c]     = make_float2(u[nt][0], u[nt][1]);
        *(float2*)&g_part[0][s][k + 8][c] = make_float2(u[nt][2], u[nt][3]);
        *(float2*)&g_part[1][s][k][c]     = make_float2(v[nt][0], v[nt][1]);
        *(float2*)&g_part[1][s][k + 8][c] = make_float2(v[nt][2], v[nt][3]);
    }
}

// ---------------------------------------------------------------------------
// Kernel 2a: reduce partials over splits, scale row k by TT = Ritz[k]^ld.
// ---------------------------------------------------------------------------
__global__ __launch_bounds__(256) void k2a_reduce(
    const float* __restrict__ Ritz, const int* __restrict__ ldp, int nsplit)
{
    __shared__ float red[256];
    const int o   = threadIdx.x & 31;
    const int seg = threadIdx.x >> 5;
    const int t   = blockIdx.x * 32 + o;
    const int uv  = t >> 13;
    const int rem = t & 8191;

    const float* p = &g_part[uv][0][0][0] + rem;
    float sum = 0.f;
    for (int s2 = seg; s2 < nsplit; s2 += 8) sum += p[(long)s2 * 8192];
    red[threadIdx.x] = sum;
    __syncthreads();

    if (threadIdx.x < 32) {
        #pragma unroll
        for (int g = 1; g < 8; g++) sum += red[g * 32 + o];
        int k = rem >> 7;
        int ld = *ldp;
        float rz = Ritz[k];
        float tt = 1.f;
        for (int i = 0; i < ld; i++) tt *= rz;
        (&g_UV[0][0][0])[t] = tt * sum;
    }
}

// ---------------------------------------------------------------------------
// Kernel 2b: P = U' @ W, R = V' @ W  ([64,128]@[128,128]); fp16 outputs.
// ---------------------------------------------------------------------------
__global__ __launch_bounds__(256) void k2b_pr(const float* __restrict__ W)
{
    __shared__ float sA[64 * 68];
    __shared__ float sW[64 * 64];

    const int m   = blockIdx.x;
    const int cp0 = blockIdx.y * 64;
    const int tx = threadIdx.x, ty = threadIdx.y;
    const int tid = ty * 16 + tx;

    float acc[4][4] = {};

    for (int cc = 0; cc < 128; cc += 64) {
        #pragma unroll
        for (int q = 0; q < 4; q++) {
            int f   = tid + 256 * q;
            int row = f >> 4;
            int c4  = (f & 15) * 4;
            *(float4*)&sA[row * 68 + c4] = *(const float4*)&g_UV[m][row][cc + c4];
            *(float4*)&sW[row * 64 + c4] = *(const float4*)(W + (cc + row) * 128 + cp0 + c4);
        }
        __syncthreads();

        #pragma unroll 4
        for (int r = 0; r < 64; r++) {
            float a[4];
            #pragma unroll
            for (int i = 0; i < 4; i++) a[i] = sA[(ty * 4 + i) * 68 + r];
            float4 w4 = *(float4*)&sW[r * 64 + tx * 4];
            float wj[4] = {w4.x, w4.y, w4.z, w4.w};
            #pragma unroll
            for (int i = 0; i < 4; i++)
                #pragma unroll
                for (int j = 0; j < 4; j++)
                    acc[i][j] += a[i] * wj[j];
        }
        __syncthreads();
    }

    unsigned short (*Dh)[128] = (m == 0) ? g_Ph : g_Rh;
    #pragma unroll
    for (int i = 0; i < 4; i++) {
        int k = ty * 4 + i;
        int c = cp0 + tx * 4;
        ((uint32_t*)&Dh[k][c])[0] = pkh2(acc[i][0], acc[i][1]);
        ((uint32_t*)&Dh[k][c])[1] = pkh2(acc[i][2], acc[i][3]);
    }
}

// ---------------------------------------------------------------------------
// Kernel 3: fp16 single-pass, latency-engineered.
// grid (ceil(N/64), 2 c-halves), block 256, 2 CTA/SM (16 warps/SM):
// 8 warps = 4 n-slabs(16) x 2 c-sub(32).
// Q staged full-K once; P/R double-buffered via cp.async (both phases issued
// up front); two back-to-back MMA phases; batched epilogue loads.
// ---------------------------------------------------------------------------
__global__ __launch_bounds__(256, 2) void k3_out(
    const float* __restrict__ Qr, const float* __restrict__ Qi,
    const float* __restrict__ re, const float* __restrict__ im,
    float* __restrict__ out, int N)
{
    __shared__ unsigned short sQr[64][PQ], sQi[64][PQ];       // 18.4 KB
    __shared__ unsigned short sPR[2][2][32][PQ];              // 18.4 KB

    const int n0 = blockIdx.x * 64;
    const int c0 = blockIdx.y * 64;
    const int tid = threadIdx.x;
    const float4 f4z = make_float4(0.f, 0.f, 0.f, 0.f);

    const int lane = tid & 31, warp = tid >> 5;
    const int slab = warp & 3;            // n-slab of 16
    const int csub = warp >> 2;           // c-sub of 32
    const int arow = slab * 16 + (lane & 15);
    const int acol8 = (lane >> 4) * 8;
    const int brow = lane & 15;
    const int gid = lane >> 2, tig = lane & 3;

    const int prow = tid >> 3, pcu = tid & 7;   // P/R staging coords

    // ---- issue both P/R phases via cp.async (groups g0, g1) ----
    cpa16(&sPR[0][0][prow][pcu * 8], &g_Ph[prow][c0 + pcu * 8]);
    cpa16(&sPR[0][1][prow][pcu * 8], &g_Rh[prow][c0 + pcu * 8]);
    cpa_commit();                                   // g0 (phase 0)
    cpa16(&sPR[1][0][prow][pcu * 8], &g_Ph[32 + prow][c0 + pcu * 8]);
    cpa16(&sPR[1][1][prow][pcu * 8], &g_Rh[32 + prow][c0 + pcu * 8]);
    cpa_commit();                                   // g1 (phase 1)

    // ---- Q full-K: LDG (batched, high MLP) -> convert -> STS ----
    float4 qa[4], qb[4];
    #pragma unroll
    for (int q = 0; q < 4; q++) {
        int f = tid + 256 * q;
        int row = f >> 4, k4 = (f & 15) * 4;
        int n = n0 + row;
        bool ok = (n < N);
        qa[q] = ok ? *(const float4*)(Qr + (long)n * 64 + k4) : f4z;
        qb[q] = ok ? *(const float4*)(Qi + (long)n * 64 + k4) : f4z;
    }
    #pragma unroll
    for (int q = 0; q < 4; q++) {
        int f = tid + 256 * q;
        int row = f >> 4, k4 = (f & 15) * 4;
        cvsth(&sQr[row][k4], qa[q]);
        cvsth(&sQi[row][k4], qb[q]);
    }

    float sr[4][4] = {};
    float si[4][4] = {};

    cpa_wait<1>();        // g0 complete
    __syncthreads();      // Q + phase-0 P/R visible to all warps

    // ---- MMA phase 0 ----
    #pragma unroll
    for (int ks = 0; ks < 2; ks++) {
        const int k0 = ks * 16;
        uint32_t qr[4], qi[4], nq[4];
        ldmA(qr, sadr(&sQr[arow][k0 + acol8]));
        ldmA(qi, sadr(&sQi[arow][k0 + acol8]));
        NEG4H(nq, qr);
        #pragma unroll
        for (int nt = 0; nt < 4; nt++) {
            uint32_t p[2], r[2];
            ldmBT(p, sadr(&sPR[0][0][k0 + brow][csub * 32 + nt * 8]));
            ldmBT(r, sadr(&sPR[0][1][k0 + brow][csub * 32 + nt * 8]));
            mma_h(sr[nt], qr, p);
            mma_h(sr[nt], qi, r);
            mma_h(si[nt], qi, p);
            mma_h(si[nt], nq, r);
        }
    }

    cpa_wait<0>();        // g1 complete
    __syncthreads();      // phase-1 P/R visible

    // ---- MMA phase 1 ----
    #pragma unroll
    for (int ks = 0; ks < 2; ks++) {
        const int k0 = ks * 16;
        uint32_t qr[4], qi[4], nq[4];
        ldmA(qr, sadr(&sQr[arow][32 + k0 + acol8]));
        ldmA(qi, sadr(&sQi[arow][32 + k0 + acol8]));
        NEG4H(nq, qr);
        #pragma unroll
        for (int nt = 0; nt < 4; nt++) {
            uint32_t p[2], r[2];
            ldmBT(p, sadr(&sPR[1][0][k0 + brow][csub * 32 + nt * 8]));
            ldmBT(r, sadr(&sPR[1][1][k0 + brow][csub * 32 + nt * 8]));
            mma_h(sr[nt], qr, p);
            mma_h(sr[nt], qi, r);
            mma_h(si[nt], qi, p);
            mma_h(si[nt], nq, r);
        }
    }

    // ---- epilogue: batched re/im loads (high MLP), masked-ReLU, store ----
    const long NC = (long)N * 128;
    float2 rl[4][2], il[4][2];
    #pragma unroll
    for (int nt = 0; nt < 4; nt++) {
        int c = c0 + csub * 32 + nt * 8 + tig * 2;
        #pragma unroll
        for (int h = 0; h < 2; h++) {
            int n = n0 + slab * 16 + gid + 8 * h;
            if (n < N) {
                long base = (long)n * 128 + c;
                rl[nt][h] = *(const float2*)(re + base);
                il[nt][h] = *(const float2*)(im + base);
            }
        }
    }
    #pragma unroll
    for (int nt = 0; nt < 4; nt++) {
        int c = c0 + csub * 32 + nt * 8 + tig * 2;
        #pragma unroll
        for (int h = 0; h < 2; h++) {
            int n = n0 + slab * 16 + gid + 8 * h;
            if (n >= N) continue;
            long base = (long)n * 128 + c;
            float sr0 = sr[nt][2 * h + 0], sr1 = sr[nt][2 * h + 1];
            float si0 = si[nt][2 * h + 0], si1 = si[nt][2 * h + 1];
            float mk0 = (sr0 >= 0.f) ? 1.f : 0.f;
            float mk1 = (sr1 >= 0.f) ? 1.f : 0.f;
            *(float2*)(out + base)      = make_float2(rl[nt][h].x + mk0 * sr0,
                                                      rl[nt][h].y + mk1 * sr1);
            *(float2*)(out + NC + base) = make_float2(il[nt][h].x + mk0 * si0,
                                                      il[nt][h].y + mk1 * si1);
        }
    }
}

// ---------------------------------------------------------------------------
extern "C" void kernel_launch(void* const* d_in, const int* in_sizes, int n_in,
                              void* d_out, int out_size)
{
    const float* real  = (const float*)d_in[0];
    const float* imag  = (const float*)d_in[1];
    const float* Qreal = (const float*)d_in[2];
    const float* Qimag = (const float*)d_in[3];
    const float* Ritz  = (const float*)d_in[4];
    const float* W     = (const float*)d_in[5];
    const int*   ldp   = (const int*)d_in[6];
    float* out = (float*)d_out;

    int N = in_sizes[0] / CDIM;
    int nchunks = (N + 31) / 32;
    int nsplit = (nchunks < NS1) ? nchunks : NS1;

    k1_partial<<<dim3(NS1, 2), 256>>>(Qreal, Qimag, real, imag, N);
    k2a_reduce<<<512, 256>>>(Ritz, ldp, nsplit);
    k2b_pr<<<dim3(2, 2), dim3(16, 16)>>>(W);
    k3_out<<<dim3((N + 63) / 64, 2), 256>>>(Qreal, Qimag, real, imag, out, N);
}